// round 10
// baseline (speedup 1.0000x reference)
#include <cuda_runtime.h>

#define NMAX 100000
#define EMAX 1600000
#define D 16
#define DEGMAX 96

// ---------------- scratch (static __device__, no allocation) ----------------
__device__ float  g_h_node[NMAX * D];
__device__ float  g_h_node_sca[NMAX * D];
__device__ float  g_hv[NMAX * D * 3];
__device__ float4 g_nrow[NMAX * 16];         // per-node 256B row: [12x float4 avh | 16 floats lgdst]
__device__ float4 g_recA[(size_t)NMAX * DEGMAX];   // (dist, ev.xyz) padded slots
__device__ float4 g_recB[(size_t)NMAX * DEGMAX];   // edge_sca padded slots
__device__ int    g_rdst[(size_t)NMAX * DEGMAX];
__device__ int    g_fill[NMAX];
__device__ float  g_emb[NMAX * D];           // emb_sca (softmax-normalized)
__device__ float  g_evx[NMAX * D];           // emb_vec SoA
__device__ float  g_evy[NMAX * D];
__device__ float  g_evz[NMAX * D];

// ---------------- per-node feature precompute (also zeroes g_fill) ----------------
__global__ void k_node(const float* __restrict__ node_sca,
                       const float* __restrict__ node_vec,
                       const float* __restrict__ W_node,  const float* __restrict__ b_node,
                       const float* __restrict__ W_node_sca, const float* __restrict__ b_node_sca,
                       const float* __restrict__ W_node_vec,
                       const float* __restrict__ W_vec_attn, const float* __restrict__ b_vec_attn,
                       const float* __restrict__ W_sca_attn,
                       int n)
{
    int t = blockIdx.x * blockDim.x + threadIdx.x;
    if (t < n) g_fill[t] = 0;
    if (t >= n * D) return;
    int nid = t >> 4, d = t & 15;
    const float* ns = node_sca + nid * 13;
    float h = b_node[d], hs = b_node_sca[d], lgd = 0.f;
#pragma unroll
    for (int c = 0; c < 13; c++) {
        float x = ns[c];
        h   += W_node[d * 13 + c] * x;
        hs  += W_node_sca[d * 13 + c] * x;
        lgd += W_sca_attn[d * 27 + 13 + c] * x;
    }
    g_h_node[t] = h;
    g_h_node_sca[t] = hs;
    float* nrow = (float*)(g_nrow + nid * 16);
    nrow[48 + d] = lgd;
    float w0 = W_node_vec[d * 2], w1 = W_node_vec[d * 2 + 1];
    float a0 = W_vec_attn[d * 2], a1 = W_vec_attn[d * 2 + 1], bv = b_vec_attn[d];
#pragma unroll
    for (int k = 0; k < 3; k++) {
        float n0 = node_vec[nid * 6 + k];
        float n1 = node_vec[nid * 6 + 3 + k];
        g_hv[t * 3 + k]  = w0 * n0 + w1 * n1;
        nrow[d * 3 + k]  = a0 * n0 + a1 * n1 + bv;
    }
}

// ---------------- scatter into padded per-node slots ----------------
__global__ void __launch_bounds__(256) k_scatter(
        const int* __restrict__ edge_index,
        const float* __restrict__ node_pos,
        const float* __restrict__ edge_sca,
        const float* __restrict__ edge_vec, int ne) {
    int e = blockIdx.x * blockDim.x + threadIdx.x;
    if (e >= ne) return;
    int s = edge_index[e];
    int t = edge_index[ne + e];
    int slot = atomicAdd(&g_fill[s], 1);
    if (slot >= DEGMAX) return;
    size_t p = (size_t)s * DEGMAX + slot;

    float dx = node_pos[s * 3]     - node_pos[t * 3];
    float dy = node_pos[s * 3 + 1] - node_pos[t * 3 + 1];
    float dz = node_pos[s * 3 + 2] - node_pos[t * 3 + 2];
    float dist = sqrtf(dx * dx + dy * dy + dz * dz);

    const float* ev = edge_vec + e * 3;
    g_recA[p] = make_float4(dist, ev[0], ev[1], ev[2]);
    g_recB[p] = *(const float4*)(edge_sca + e * 4);
    g_rdst[p] = t;
}

// ---------------- edge aggregation: warp per node, online softmax ----------------
__global__ void __launch_bounds__(256, 6) k_edge(
    const float* __restrict__ node_sca,
    const float* __restrict__ W_sca_attn, const float* __restrict__ b_sca_attn,
    const float* __restrict__ W_edge,     const float* __restrict__ b_edge,
    const float* __restrict__ W_edge_sca, const float* __restrict__ b_edge_sca,
    const float* __restrict__ W_edge_vec, int n)
{
    int gw = (blockIdx.x * blockDim.x + threadIdx.x) >> 5;
    if (gw >= n) return;
    int lane = threadIdx.x & 31, d = lane & 15, half = lane >> 4;
    int lcap = min(d, 11);
    float lmask = (d < 12) ? 1.f : 0.f;
    int nid = gw;

    float lbase = b_sca_attn[d];
    {
        const float* ns = node_sca + nid * 13;
#pragma unroll
        for (int c = 0; c < 13; c++) lbase += W_sca_attn[d * 27 + c] * ns[c];
    }
    float wdist = W_sca_attn[d * 27 + 26];
    float We0 = W_edge[d * 4], We1 = W_edge[d * 4 + 1], We2 = W_edge[d * 4 + 2], We3 = W_edge[d * 4 + 3];
    float Ws0 = W_edge_sca[d * 4], Ws1 = W_edge_sca[d * 4 + 1], Ws2 = W_edge_sca[d * 4 + 2], Ws3 = W_edge_sca[d * 4 + 3];
    float be = b_edge[d], bes = b_edge_sca[d];
    float hn = g_h_node[nid * 16 + d];
    float hnswev = g_h_node_sca[nid * 16 + d] * W_edge_vec[d];
    float hv0 = g_hv[(nid * 16 + d) * 3 + 0];
    float hv1 = g_hv[(nid * 16 + d) * 3 + 1];
    float hv2 = g_hv[(nid * 16 + d) * 3 + 2];
    float4 as4 = g_nrow[nid * 16 + lcap];
    as4.x *= lmask; as4.y *= lmask; as4.z *= lmask; as4.w *= lmask;

    size_t beg = (size_t)nid * DEGMAX;
    int cnt = min(g_fill[nid], DEGMAX);

    float m = -1e30f, s = 0.f, acc = 0.f;
    float vxA = 0.f, vyA = 0.f, vzA = 0.f;

#pragma unroll 4
    for (int ii = 0; ii < cnt; ii += 2) {
        int my = ii + half;
        bool act = my < cnt;
        size_t idx = beg + min(my, cnt - 1);
        int dst = g_rdst[idx];
        float4 ra = g_recA[idx];
        float4 es = g_recB[idx];
        const float* drow = (const float*)(g_nrow + dst * 16);
        float lg = lbase + wdist * ra.x + drow[48 + d];
        float4 at4 = g_nrow[dst * 16 + lcap];
        float pd = as4.x * at4.x + as4.y * at4.y + as4.z * at4.z + as4.w * at4.w;
        pd += __shfl_xor_sync(0xffffffffu, pd, 1);
        pd += __shfl_xor_sync(0xffffffffu, pd, 2);
        pd += __shfl_xor_sync(0xffffffffu, pd, 4);
        pd += __shfl_xor_sync(0xffffffffu, pd, 8);
        float avw = 1.f / (1.f + __expf(-pd));
        float eh1 = be  + We0 * es.x + We1 * es.y + We2 * es.z + We3 * es.w;
        float eh2 = bes + Ws0 * es.x + Ws1 * es.y + Ws2 * es.z + Ws3 * es.w;
        float msca = hn * eh1;
        float mn = fmaxf(m, lg);
        float scale = __expf(m - mn);
        float p = __expf(lg - mn);
        float c1 = hnswev * avw, c2 = eh2 * avw;
        if (act) {
            m = mn;
            s = s * scale + p;
            acc = acc * scale + p * msca;
            vxA += c1 * ra.y + c2 * hv0;
            vyA += c1 * ra.z + c2 * hv1;
            vzA += c1 * ra.w + c2 * hv2;
        }
    }

    // merge the two half-warp softmax states
    float m2 = __shfl_xor_sync(0xffffffffu, m, 16);
    float s2 = __shfl_xor_sync(0xffffffffu, s, 16);
    float a2 = __shfl_xor_sync(0xffffffffu, acc, 16);
    float mm = fmaxf(m, m2);
    float f1 = __expf(m - mm), f2 = __expf(m2 - mm);
    s = s * f1 + s2 * f2;
    acc = acc * f1 + a2 * f2;
    vxA += __shfl_xor_sync(0xffffffffu, vxA, 16);
    vyA += __shfl_xor_sync(0xffffffffu, vyA, 16);
    vzA += __shfl_xor_sync(0xffffffffu, vzA, 16);

    if (half == 0) {
        int t = nid * 16 + d;
        g_emb[t] = (s > 0.f) ? acc / s : 0.f;
        g_evx[t] = vxA;
        g_evy[t] = vyA;
        g_evz[t] = vzA;
    }
}

// ---------------- epilogue: GVPerceptron + VN leaky, warp per node ----------------
__global__ void __launch_bounds__(256) k_post(
    const float* __restrict__ W_gv_vec1, const float* __restrict__ W_gv_vec2,
    const float* __restrict__ W_gv_sca,  const float* __restrict__ W_gate,
    const float* __restrict__ b_gate,    const float* __restrict__ W_dir,
    float* __restrict__ out, int n)
{
    __shared__ float sW1[256], sW2[256], sWg[256], sWd[256], sWgs[512], sbg[16];
    for (int i = threadIdx.x; i < 256; i += blockDim.x) {
        int o = i >> 4, j = i & 15;
        sW1[j * 16 + o] = W_gv_vec1[i];
        sW2[j * 16 + o] = W_gv_vec2[i];
        sWg[j * 16 + o] = W_gate[i];
        sWd[j * 16 + o] = W_dir[i];
    }
    for (int i = threadIdx.x; i < 512; i += blockDim.x) {
        int o = i >> 5, j = i & 31;
        sWgs[j * 16 + o] = W_gv_sca[i];
    }
    if (threadIdx.x < 16) sbg[threadIdx.x] = b_gate[threadIdx.x];
    __syncthreads();

    int gw = (blockIdx.x * blockDim.x + threadIdx.x) >> 5;
    if (gw >= n) return;
    int lane = threadIdx.x & 31, d = lane & 15, half = lane >> 4;
    int nid = gw;
    int t16 = nid * 16 + d;

    float emb = g_emb[t16];
    float vxA = g_evx[t16], vyA = g_evy[t16], vzA = g_evz[t16];

    float v1x = 0.f, v1y = 0.f, v1z = 0.f;
#pragma unroll
    for (int j = 0; j < 16; j++) {
        float w = sW1[j * 16 + d];
        v1x += w * __shfl_sync(0xffffffffu, vxA, j, 16);
        v1y += w * __shfl_sync(0xffffffffu, vyA, j, 16);
        v1z += w * __shfl_sync(0xffffffffu, vzA, j, 16);
    }
    float vn = sqrtf(v1x * v1x + v1y * v1y + v1z * v1z + 1e-12f);
    float osca = 0.f;
#pragma unroll
    for (int j = 0; j < 16; j++) {
        osca += sWgs[j * 16 + d] * __shfl_sync(0xffffffffu, vn, j, 16);
        osca += sWgs[(16 + j) * 16 + d] * __shfl_sync(0xffffffffu, emb, j, 16);
    }
    float gt = sbg[d];
#pragma unroll
    for (int j = 0; j < 16; j++)
        gt += sWg[j * 16 + d] * __shfl_sync(0xffffffffu, osca, j, 16);
    gt = 1.f / (1.f + __expf(-gt));
    float ox = 0.f, oy = 0.f, oz = 0.f;
#pragma unroll
    for (int j = 0; j < 16; j++) {
        float w = sW2[j * 16 + d];
        ox += w * __shfl_sync(0xffffffffu, v1x, j, 16);
        oy += w * __shfl_sync(0xffffffffu, v1y, j, 16);
        oz += w * __shfl_sync(0xffffffffu, v1z, j, 16);
    }
    ox *= gt; oy *= gt; oz *= gt;
    float osca_o = (osca >= 0.f) ? osca : 0.2f * osca;
    float dxv = 0.f, dyv = 0.f, dzv = 0.f;
#pragma unroll
    for (int j = 0; j < 16; j++) {
        float w = sWd[j * 16 + d];
        dxv += w * __shfl_sync(0xffffffffu, ox, j, 16);
        dyv += w * __shfl_sync(0xffffffffu, oy, j, 16);
        dzv += w * __shfl_sync(0xffffffffu, oz, j, 16);
    }
    float dot = ox * dxv + oy * dyv + oz * dzv;
    float dd = dxv * dxv + dyv * dyv + dzv * dzv + 1e-6f;
    float tt = dot / dd;
    float prx = ox - tt * dxv, pry = oy - tt * dyv, prz = oz - tt * dzv;
    float fx = 0.2f * ox + 0.8f * ((dot >= 0.f) ? ox : prx);
    float fy = 0.2f * oy + 0.8f * ((dot >= 0.f) ? oy : pry);
    float fz = 0.2f * oz + 0.8f * ((dot >= 0.f) ? oz : prz);

    if (half == 0) {
        out[t16] = osca_o;
        size_t base = (size_t)n * 16 + (size_t)t16 * 3;
        out[base + 0] = fx;
        out[base + 1] = fy;
        out[base + 2] = fz;
    }
}

// ---------------- launch ----------------
extern "C" void kernel_launch(void* const* d_in, const int* in_sizes, int n_in,
                              void* d_out, int out_size)
{
    const float* node_sca   = (const float*)d_in[0];
    const float* node_vec   = (const float*)d_in[1];
    const float* node_pos   = (const float*)d_in[2];
    const float* edge_sca   = (const float*)d_in[3];
    const float* edge_vec   = (const float*)d_in[4];
    const int*   edge_index = (const int*)  d_in[5];
    const float* W_sca_attn = (const float*)d_in[6];
    const float* b_sca_attn = (const float*)d_in[7];
    const float* W_vec_attn = (const float*)d_in[8];
    const float* b_vec_attn = (const float*)d_in[9];
    const float* W_node     = (const float*)d_in[10];
    const float* b_node     = (const float*)d_in[11];
    const float* W_edge     = (const float*)d_in[12];
    const float* b_edge     = (const float*)d_in[13];
    const float* W_node_sca = (const float*)d_in[14];
    const float* b_node_sca = (const float*)d_in[15];
    const float* W_node_vec = (const float*)d_in[16];
    const float* W_edge_sca = (const float*)d_in[17];
    const float* b_edge_sca = (const float*)d_in[18];
    const float* W_edge_vec = (const float*)d_in[19];
    const float* W_gv_vec1  = (const float*)d_in[20];
    const float* W_gv_vec2  = (const float*)d_in[21];
    const float* W_gv_sca   = (const float*)d_in[22];
    const float* W_gate     = (const float*)d_in[23];
    const float* b_gate     = (const float*)d_in[24];
    const float* W_dir      = (const float*)d_in[25];

    int n  = in_sizes[2] / 3;   // node_pos
    int ne = in_sizes[5] / 2;   // edge_index

    k_node<<<(n * D + 127) / 128, 128>>>(node_sca, node_vec,
                                         W_node, b_node, W_node_sca, b_node_sca,
                                         W_node_vec, W_vec_attn, b_vec_attn,
                                         W_sca_attn, n);
    k_scatter<<<(ne + 255) / 256, 256>>>(edge_index, node_pos, edge_sca, edge_vec, ne);
    k_edge<<<(n + 7) / 8, 256>>>(node_sca, W_sca_attn, b_sca_attn, W_edge, b_edge,
                                 W_edge_sca, b_edge_sca, W_edge_vec, n);
    k_post<<<(n + 7) / 8, 256>>>(W_gv_vec1, W_gv_vec2, W_gv_sca, W_gate, b_gate, W_dir,
                                 (float*)d_out, n);
}

// round 11
// speedup vs baseline: 1.2852x; 1.2852x over previous
#include <cuda_runtime.h>

#define NMAX 100000
#define EMAX 1600000
#define D 16
#define DEGMAX 96

// ---------------- scratch (static __device__, no allocation) ----------------
__device__ float  g_h_node[NMAX * D];
__device__ float  g_h_node_sca[NMAX * D];
__device__ float  g_hv[NMAX * D * 3];
__device__ float4 g_nrow[NMAX * 16];         // per-node 256B row: [12x float4 avh | 16 floats lgdst]
__device__ float4 g_recA[(size_t)NMAX * DEGMAX];   // (dist, ev.xyz) padded slots
__device__ float4 g_recB[(size_t)NMAX * DEGMAX];   // edge_sca padded slots
__device__ int    g_rdst[(size_t)NMAX * DEGMAX];
__device__ int    g_fill[NMAX];
__device__ float  g_emb[NMAX * D];           // emb_sca (softmax-normalized)
__device__ float  g_evx[NMAX * D];           // emb_vec SoA
__device__ float  g_evy[NMAX * D];
__device__ float  g_evz[NMAX * D];

// ---------------- per-node feature precompute (also zeroes g_fill) ----------------
__global__ void k_node(const float* __restrict__ node_sca,
                       const float* __restrict__ node_vec,
                       const float* __restrict__ W_node,  const float* __restrict__ b_node,
                       const float* __restrict__ W_node_sca, const float* __restrict__ b_node_sca,
                       const float* __restrict__ W_node_vec,
                       const float* __restrict__ W_vec_attn, const float* __restrict__ b_vec_attn,
                       const float* __restrict__ W_sca_attn,
                       int n)
{
    int t = blockIdx.x * blockDim.x + threadIdx.x;
    if (t < n) g_fill[t] = 0;
    if (t >= n * D) return;
    int nid = t >> 4, d = t & 15;
    const float* ns = node_sca + nid * 13;
    float h = b_node[d], hs = b_node_sca[d], lgd = 0.f;
#pragma unroll
    for (int c = 0; c < 13; c++) {
        float x = ns[c];
        h   += W_node[d * 13 + c] * x;
        hs  += W_node_sca[d * 13 + c] * x;
        lgd += W_sca_attn[d * 27 + 13 + c] * x;
    }
    g_h_node[t] = h;
    g_h_node_sca[t] = hs;
    float* nrow = (float*)(g_nrow + nid * 16);
    nrow[48 + d] = lgd;
    float w0 = W_node_vec[d * 2], w1 = W_node_vec[d * 2 + 1];
    float a0 = W_vec_attn[d * 2], a1 = W_vec_attn[d * 2 + 1], bv = b_vec_attn[d];
#pragma unroll
    for (int k = 0; k < 3; k++) {
        float n0 = node_vec[nid * 6 + k];
        float n1 = node_vec[nid * 6 + 3 + k];
        g_hv[t * 3 + k]  = w0 * n0 + w1 * n1;
        nrow[d * 3 + k]  = a0 * n0 + a1 * n1 + bv;
    }
}

// ---------------- scatter into padded per-node slots ----------------
__global__ void __launch_bounds__(256) k_scatter(
        const int* __restrict__ edge_index,
        const float* __restrict__ node_pos,
        const float* __restrict__ edge_sca,
        const float* __restrict__ edge_vec, int ne) {
    int e = blockIdx.x * blockDim.x + threadIdx.x;
    if (e >= ne) return;
    int s = edge_index[e];
    int t = edge_index[ne + e];
    int slot = atomicAdd(&g_fill[s], 1);
    if (slot >= DEGMAX) return;
    size_t p = (size_t)s * DEGMAX + slot;

    float dx = node_pos[s * 3]     - node_pos[t * 3];
    float dy = node_pos[s * 3 + 1] - node_pos[t * 3 + 1];
    float dz = node_pos[s * 3 + 2] - node_pos[t * 3 + 2];
    float dist = sqrtf(dx * dx + dy * dy + dz * dz);

    const float* ev = edge_vec + e * 3;
    g_recA[p] = make_float4(dist, ev[0], ev[1], ev[2]);
    g_recB[p] = *(const float4*)(edge_sca + e * 4);
    g_rdst[p] = t;
}

// ---------------- edge aggregation: warp per node, online softmax ----------------
__global__ void __launch_bounds__(256, 6) k_edge(
    const float* __restrict__ node_sca,
    const float* __restrict__ W_sca_attn, const float* __restrict__ b_sca_attn,
    const float* __restrict__ W_edge,     const float* __restrict__ b_edge,
    const float* __restrict__ W_edge_sca, const float* __restrict__ b_edge_sca,
    const float* __restrict__ W_edge_vec, int n)
{
    int gw = (blockIdx.x * blockDim.x + threadIdx.x) >> 5;
    if (gw >= n) return;
    int lane = threadIdx.x & 31, d = lane & 15, half = lane >> 4;
    int lcap = min(d, 11);
    float lmask = (d < 12) ? 1.f : 0.f;
    int nid = gw;

    float lbase = b_sca_attn[d];
    {
        const float* ns = node_sca + nid * 13;
#pragma unroll
        for (int c = 0; c < 13; c++) lbase += W_sca_attn[d * 27 + c] * ns[c];
    }
    float wdist = W_sca_attn[d * 27 + 26];
    float We0 = W_edge[d * 4], We1 = W_edge[d * 4 + 1], We2 = W_edge[d * 4 + 2], We3 = W_edge[d * 4 + 3];
    float Ws0 = W_edge_sca[d * 4], Ws1 = W_edge_sca[d * 4 + 1], Ws2 = W_edge_sca[d * 4 + 2], Ws3 = W_edge_sca[d * 4 + 3];
    float be = b_edge[d], bes = b_edge_sca[d];
    float hn = g_h_node[nid * 16 + d];
    float hnswev = g_h_node_sca[nid * 16 + d] * W_edge_vec[d];
    float hv0 = g_hv[(nid * 16 + d) * 3 + 0];
    float hv1 = g_hv[(nid * 16 + d) * 3 + 1];
    float hv2 = g_hv[(nid * 16 + d) * 3 + 2];
    float4 as4 = g_nrow[nid * 16 + lcap];
    as4.x *= lmask; as4.y *= lmask; as4.z *= lmask; as4.w *= lmask;

    size_t beg = (size_t)nid * DEGMAX;
    int cnt = min(g_fill[nid], DEGMAX);

    float m = -1e30f, s = 0.f, acc = 0.f;
    float vxA = 0.f, vyA = 0.f, vzA = 0.f;

#pragma unroll 4
    for (int ii = 0; ii < cnt; ii += 2) {
        int my = ii + half;
        bool act = my < cnt;
        size_t idx = beg + min(my, cnt - 1);
        int dst = g_rdst[idx];
        float4 ra = g_recA[idx];
        float4 es = g_recB[idx];
        const float* drow = (const float*)(g_nrow + dst * 16);
        float lg = lbase + wdist * ra.x + drow[48 + d];
        float4 at4 = g_nrow[dst * 16 + lcap];
        float pd = as4.x * at4.x + as4.y * at4.y + as4.z * at4.z + as4.w * at4.w;
        pd += __shfl_xor_sync(0xffffffffu, pd, 1);
        pd += __shfl_xor_sync(0xffffffffu, pd, 2);
        pd += __shfl_xor_sync(0xffffffffu, pd, 4);
        pd += __shfl_xor_sync(0xffffffffu, pd, 8);
        float avw = 1.f / (1.f + __expf(-pd));
        float eh1 = be  + We0 * es.x + We1 * es.y + We2 * es.z + We3 * es.w;
        float eh2 = bes + Ws0 * es.x + Ws1 * es.y + Ws2 * es.z + Ws3 * es.w;
        float msca = hn * eh1;
        float mn = fmaxf(m, lg);
        float scale = __expf(m - mn);
        float p = __expf(lg - mn);
        float c1 = hnswev * avw, c2 = eh2 * avw;
        if (act) {
            m = mn;
            s = s * scale + p;
            acc = acc * scale + p * msca;
            vxA += c1 * ra.y + c2 * hv0;
            vyA += c1 * ra.z + c2 * hv1;
            vzA += c1 * ra.w + c2 * hv2;
        }
    }

    // merge the two half-warp softmax states
    float m2 = __shfl_xor_sync(0xffffffffu, m, 16);
    float s2 = __shfl_xor_sync(0xffffffffu, s, 16);
    float a2 = __shfl_xor_sync(0xffffffffu, acc, 16);
    float mm = fmaxf(m, m2);
    float f1 = __expf(m - mm), f2 = __expf(m2 - mm);
    s = s * f1 + s2 * f2;
    acc = acc * f1 + a2 * f2;
    vxA += __shfl_xor_sync(0xffffffffu, vxA, 16);
    vyA += __shfl_xor_sync(0xffffffffu, vyA, 16);
    vzA += __shfl_xor_sync(0xffffffffu, vzA, 16);

    if (half == 0) {
        int t = nid * 16 + d;
        g_emb[t] = (s > 0.f) ? acc / s : 0.f;
        g_evx[t] = vxA;
        g_evy[t] = vyA;
        g_evz[t] = vzA;
    }
}

// ---------------- epilogue: thread per node, register-resident 16x16 matmuls ----------------
__global__ void __launch_bounds__(128) k_post(
    const float* __restrict__ W_gv_vec1, const float* __restrict__ W_gv_vec2,
    const float* __restrict__ W_gv_sca,  const float* __restrict__ W_gate,
    const float* __restrict__ b_gate,    const float* __restrict__ W_dir,
    float* __restrict__ out, int n)
{
    // weights in smem, natural [o][j] layout (broadcast reads, conflict-free)
    __shared__ float sW1[256], sW2[256], sWg[256], sWd[256], sWgs[512], sbg[16];
    for (int i = threadIdx.x; i < 256; i += blockDim.x) {
        sW1[i] = W_gv_vec1[i];
        sW2[i] = W_gv_vec2[i];
        sWg[i] = W_gate[i];
        sWd[i] = W_dir[i];
    }
    for (int i = threadIdx.x; i < 512; i += blockDim.x) sWgs[i] = W_gv_sca[i];
    if (threadIdx.x < 16) sbg[threadIdx.x] = b_gate[threadIdx.x];
    __syncthreads();

    int nid = blockIdx.x * blockDim.x + threadIdx.x;
    if (nid >= n) return;
    int t16 = nid * 16;

    float emb[16], evx[16], evy[16], evz[16];
#pragma unroll
    for (int j = 0; j < 16; j += 4) {
        *(float4*)(emb + j) = *(const float4*)(g_emb + t16 + j);
        *(float4*)(evx + j) = *(const float4*)(g_evx + t16 + j);
        *(float4*)(evy + j) = *(const float4*)(g_evy + t16 + j);
        *(float4*)(evz + j) = *(const float4*)(g_evz + t16 + j);
    }

    // v1 = W1 @ emb_vec
    float v1x[16], v1y[16], v1z[16], vn[16];
#pragma unroll
    for (int o = 0; o < 16; o++) {
        float ax = 0.f, ay = 0.f, az = 0.f;
#pragma unroll
        for (int j = 0; j < 16; j++) {
            float w = sW1[o * 16 + j];
            ax += w * evx[j]; ay += w * evy[j]; az += w * evz[j];
        }
        v1x[o] = ax; v1y[o] = ay; v1z[o] = az;
        vn[o] = sqrtf(ax * ax + ay * ay + az * az + 1e-12f);
    }

    // out_sca = Wgs @ [vn ; emb]
    float osca[16];
#pragma unroll
    for (int o = 0; o < 16; o++) {
        float a = 0.f;
#pragma unroll
        for (int j = 0; j < 16; j++) {
            a += sWgs[o * 32 + j] * vn[j];
            a += sWgs[o * 32 + 16 + j] * emb[j];
        }
        osca[o] = a;
    }

    // gate = sigmoid(Wg @ osca + bg); out_vec = gate * (W2 @ v1)
    float ox[16], oy[16], oz[16];
#pragma unroll
    for (int o = 0; o < 16; o++) {
        float g = sbg[o];
        float ax = 0.f, ay = 0.f, az = 0.f;
#pragma unroll
        for (int j = 0; j < 16; j++) {
            g += sWg[o * 16 + j] * osca[j];
            float w = sW2[o * 16 + j];
            ax += w * v1x[j]; ay += w * v1y[j]; az += w * v1z[j];
        }
        g = 1.f / (1.f + __expf(-g));
        ox[o] = g * ax; oy[o] = g * ay; oz[o] = g * az;
    }

    // d = Wd @ out_vec; VN leaky relu; write
    float fout[48];
#pragma unroll
    for (int o = 0; o < 16; o++) {
        float dxv = 0.f, dyv = 0.f, dzv = 0.f;
#pragma unroll
        for (int j = 0; j < 16; j++) {
            float w = sWd[o * 16 + j];
            dxv += w * ox[j]; dyv += w * oy[j]; dzv += w * oz[j];
        }
        float dot = ox[o] * dxv + oy[o] * dyv + oz[o] * dzv;
        float dd = dxv * dxv + dyv * dyv + dzv * dzv + 1e-6f;
        float tt = dot / dd;
        float prx = ox[o] - tt * dxv, pry = oy[o] - tt * dyv, prz = oz[o] - tt * dzv;
        fout[o * 3 + 0] = 0.2f * ox[o] + 0.8f * ((dot >= 0.f) ? ox[o] : prx);
        fout[o * 3 + 1] = 0.2f * oy[o] + 0.8f * ((dot >= 0.f) ? oy[o] : pry);
        fout[o * 3 + 2] = 0.2f * oz[o] + 0.8f * ((dot >= 0.f) ? oz[o] : prz);
        osca[o] = (osca[o] >= 0.f) ? osca[o] : 0.2f * osca[o];
    }

#pragma unroll
    for (int j = 0; j < 16; j += 4)
        *(float4*)(out + t16 + j) = *(const float4*)(osca + j);
    float* vout = out + (size_t)n * 16 + (size_t)t16 * 3;
#pragma unroll
    for (int j = 0; j < 48; j += 4)
        *(float4*)(vout + j) = *(const float4*)(fout + j);
}

// ---------------- launch ----------------
extern "C" void kernel_launch(void* const* d_in, const int* in_sizes, int n_in,
                              void* d_out, int out_size)
{
    const float* node_sca   = (const float*)d_in[0];
    const float* node_vec   = (const float*)d_in[1];
    const float* node_pos   = (const float*)d_in[2];
    const float* edge_sca   = (const float*)d_in[3];
    const float* edge_vec   = (const float*)d_in[4];
    const int*   edge_index = (const int*)  d_in[5];
    const float* W_sca_attn = (const float*)d_in[6];
    const float* b_sca_attn = (const float*)d_in[7];
    const float* W_vec_attn = (const float*)d_in[8];
    const float* b_vec_attn = (const float*)d_in[9];
    const float* W_node     = (const float*)d_in[10];
    const float* b_node     = (const float*)d_in[11];
    const float* W_edge     = (const float*)d_in[12];
    const float* b_edge     = (const float*)d_in[13];
    const float* W_node_sca = (const float*)d_in[14];
    const float* b_node_sca = (const float*)d_in[15];
    const float* W_node_vec = (const float*)d_in[16];
    const float* W_edge_sca = (const float*)d_in[17];
    const float* b_edge_sca = (const float*)d_in[18];
    const float* W_edge_vec = (const float*)d_in[19];
    const float* W_gv_vec1  = (const float*)d_in[20];
    const float* W_gv_vec2  = (const float*)d_in[21];
    const float* W_gv_sca   = (const float*)d_in[22];
    const float* W_gate     = (const float*)d_in[23];
    const float* b_gate     = (const float*)d_in[24];
    const float* W_dir      = (const float*)d_in[25];

    int n  = in_sizes[2] / 3;   // node_pos
    int ne = in_sizes[5] / 2;   // edge_index

    k_node<<<(n * D + 127) / 128, 128>>>(node_sca, node_vec,
                                         W_node, b_node, W_node_sca, b_node_sca,
                                         W_node_vec, W_vec_attn, b_vec_attn,
                                         W_sca_attn, n);
    k_scatter<<<(ne + 255) / 256, 256>>>(edge_index, node_pos, edge_sca, edge_vec, ne);
    k_edge<<<(n + 7) / 8, 256>>>(node_sca, W_sca_attn, b_sca_attn, W_edge, b_edge,
                                 W_edge_sca, b_edge_sca, W_edge_vec, n);
    k_post<<<(n + 127) / 128, 128>>>(W_gv_vec1, W_gv_vec2, W_gv_sca, W_gate, b_gate, W_dir,
                                     (float*)d_out, n);
}